// round 13
// baseline (speedup 1.0000x reference)
#include <cuda_runtime.h>
#include <math.h>

#define N_NODES 8000
#define NT      (N_NODES * 12)        // 96000
#define NODES_PER_BLK 64
#define NBLOCKS 125                   // 8000/64, <=148 SMs -> all co-resident
#define NTHREADS 320

// Row-per-block partials: g_part[b][j]; rows 125..127 never written (stay 0.0
// from static zero-init) -> combine sums a fixed 128 rows in fixed order.
__device__ float    g_part[128][128];
__device__ unsigned g_arrive;         // monotonic epoch counter (never reset)

__global__ void __launch_bounds__(NTHREADS)
fused_kernel(const float* __restrict__ x,
             const float* __restrict__ U1,
             const float* __restrict__ U2,   // (5,8000) row-major
             const float* __restrict__ U3,
             const float* __restrict__ be,
             const float* __restrict__ Ve,
             const float* __restrict__ w,    // conv2_w (5,5,1,3) flat o*15+i*3+k
             const float* __restrict__ bias, // conv2_b (5,)
             float* __restrict__ out)
{
    __shared__ float sX [NODES_PER_BLK][61];      // x[nl][t*5+f], pad 61
    __shared__ float sX2[5][NODES_PER_BLK * 13];
    __shared__ float sQ[2][120];
    __shared__ float sU1[NODES_PER_BLK];
    __shared__ float sU2[5][NODES_PER_BLK];
    __shared__ float sU3[5];
    __shared__ float sVe[144];
    __shared__ float sBe[144];
    __shared__ float sLhs[60];
    __shared__ float sM2[60];
    __shared__ float sS[12][12];
    __shared__ float sE[12][12];
    __shared__ float sAt[12][12];
    __shared__ float sW[75];
    __shared__ float sB[5];

    const int tid = threadIdx.x;
    const int b   = blockIdx.x;
    const int n0  = b * NODES_PER_BLK;

    // ---- Preamble: x tile + ALL small tensors, one overlapped burst ----
    {
        const float4* xp = (const float4*)(x + n0 * 60);
        #pragma unroll
        for (int r = 0; r < 3; r++) {
            const int j = tid + r * NTHREADS;
            float4 v = xp[j];
            const int n = j / 15, c = (j % 15) * 4;
            float* d = &sX[n][c];
            d[0] = v.x; d[1] = v.y; d[2] = v.z; d[3] = v.w;
        }
    }
    {   // sU2 covers all 320 threads
        const int f2 = tid / NODES_PER_BLK, nl = tid % NODES_PER_BLK;
        sU2[f2][nl] = U2[f2 * N_NODES + n0 + nl];
    }
    if (tid < NODES_PER_BLK)            sU1[tid]        = U1[n0 + tid];
    if (tid < 5)                        sU3[tid]        = U3[tid];
    if (tid < 144)                      sVe[tid]        = Ve[tid];
    if (tid >= 144 && tid < 288)        sBe[tid - 144]  = be[tid - 144];
    if (tid < 75)                       sW[tid]         = w[tid];
    if (tid >= 288 && tid < 293)        sB[tid - 288]   = bias[tid - 288];
    __syncthreads();

    // ---- Block partials (120 threads), rhs folded inline ----
    //   j<60   : lhs[t*5+f]   = sum_nl sX[nl][j]*U1[nl]
    //   60..119: M2[f2*12+t]  = sum_nl U2[f2][nl]*(sum_f sX[nl][t*5+f]*U3[f])
    if (tid < 120) {
        float acc = 0.f;
        if (tid < 60) {
            #pragma unroll 8
            for (int nl = 0; nl < NODES_PER_BLK; nl++)
                acc += sX[nl][tid] * sU1[nl];
        } else {
            const int jj = tid - 60;
            const int f2 = jj / 12, t = jj % 12;
            float u3[5];
            #pragma unroll
            for (int f = 0; f < 5; f++) u3[f] = sU3[f];
            #pragma unroll 4
            for (int nl = 0; nl < NODES_PER_BLK; nl++) {
                float r = 0.f;
                #pragma unroll
                for (int f = 0; f < 5; f++) r += sX[nl][t * 5 + f] * u3[f];
                acc += sU2[f2][nl] * r;
            }
        }
        g_part[b][tid] = acc;            // coalesced 120-float row
    }
    __syncthreads();                     // order STGs before release fence

    // ---- Grid barrier: single release fence + monotonic epoch spin ----
    if (tid == 0) {
        __threadfence();                 // release partials (one MEMBAR.GPU)
        unsigned old = atomicAdd(&g_arrive, 1u);
        const unsigned target = (old / (unsigned)NBLOCKS + 1u) * (unsigned)NBLOCKS;
        volatile unsigned* va = &g_arrive;
        while (*va < target) { }
        __threadfence();                 // acquire
    }
    __syncthreads();

    // ---- Combine: (half q, j) sums 64 fixed rows, warp-coalesced ----
    if (tid < 240) {
        const int q = tid / 120, j = tid % 120;
        const float* p = &g_part[q * 64][0];
        float s = 0.f;
        #pragma unroll 16
        for (int i = 0; i < 64; i++)
            s += __ldcg(p + i * 128 + j);          // rows 125..127 read as 0
        sQ[q][j] = s;
    }
    __syncthreads();
    if (tid < 120) {
        float s = sQ[0][tid] + sQ[1][tid];
        if (tid < 60) sLhs[tid] = s;
        else          sM2[tid - 60] = s;
    }
    __syncthreads();

    // ---- At2 distributed: 144-thread phases ----
    if (tid < 144) {
        const int t1 = tid / 12, t2 = tid % 12;
        float p = 0.f;
        #pragma unroll
        for (int f = 0; f < 5; f++) p += sLhs[t1 * 5 + f] * sM2[f * 12 + t2];
        p += sBe[tid];
        sS[t1][t2] = 1.f / (1.f + __expf(-p));
    }
    __syncthreads();
    if (tid < 144) {
        const int t1 = tid / 12, t2 = tid % 12;
        float e = 0.f;
        #pragma unroll
        for (int k = 0; k < 12; k++) e += sVe[t1 * 12 + k] * sS[k][t2];
        sE[t1][t2] = e;
    }
    __syncthreads();
    if (tid < 12) {                               // column softmax
        const int t2 = tid;
        float E[12];
        float mx = -1e30f;
        #pragma unroll
        for (int k = 0; k < 12; k++) { E[k] = sE[k][t2]; mx = fmaxf(mx, E[k]); }
        float den = 0.f;
        #pragma unroll
        for (int k = 0; k < 12; k++) { E[k] = __expf(E[k] - mx); den += E[k]; }
        const float inv = 1.f / den;
        #pragma unroll
        for (int k = 0; k < 12; k++) sAt[k][t2] = E[k] * inv;
    }
    __syncthreads();

    // ---- Phase B: thread (f, nl) -> x2[f][nl][0..11] ----
    {
        const int f  = tid / NODES_PER_BLK;
        const int nl = tid % NODES_PER_BLK;
        float xr[12];
        #pragma unroll
        for (int tp = 0; tp < 12; tp++) xr[tp] = sX[nl][tp * 5 + f];
        float* dst = &sX2[f][nl * 13];
        #pragma unroll
        for (int t = 0; t < 12; t++) {
            float a = 0.f;
            #pragma unroll
            for (int tp = 0; tp < 12; tp++) a += xr[tp] * sAt[tp][t];
            dst[t] = a;
        }
    }
    __syncthreads();

    // ---- Phase C: thread (o, nl) -> conv plane + coalesced 48B store ----
    {
        const int o  = tid / NODES_PER_BLK;
        const int nl = tid % NODES_PER_BLK;
        float wr[15];
        #pragma unroll
        for (int i = 0; i < 15; i++) wr[i] = sW[o * 15 + i];
        const float b0 = sB[o];

        float yr[12];
        #pragma unroll
        for (int t = 0; t < 12; t++) yr[t] = b0;
        #pragma unroll
        for (int fi = 0; fi < 5; fi++) {
            const float* s = &sX2[fi][nl * 13];
            float v[12];
            #pragma unroll
            for (int t = 0; t < 12; t++) v[t] = s[t];
            const float w0 = wr[fi * 3 + 0], w1 = wr[fi * 3 + 1], w2 = wr[fi * 3 + 2];
            #pragma unroll
            for (int t = 0; t < 12; t++) {
                float a = w1 * v[t];
                if (t > 0)  a += w0 * v[t - 1];
                if (t < 11) a += w2 * v[t + 1];
                yr[t] += a;
            }
        }
        // raw-reshape output: flat = o*N*T + n*T + t
        float4* op = (float4*)(out + o * NT + (n0 + nl) * 12);
        op[0] = make_float4(yr[0], yr[1], yr[2],  yr[3]);
        op[1] = make_float4(yr[4], yr[5], yr[6],  yr[7]);
        op[2] = make_float4(yr[8], yr[9], yr[10], yr[11]);
    }
}

extern "C" void kernel_launch(void* const* d_in, const int* in_sizes, int n_in,
                              void* d_out, int out_size)
{
    // metadata order: x, adj, U1_1, U2_1, U3_1, be_1, Ve_1,
    //                 U1_2, U2_2, U3_2, be_2, Ve_2,
    //                 conv1_w, conv1_b, conv2_w, conv2_b, W_hgc, b_hgc
    const float* x    = (const float*)d_in[0];
    const float* U1_2 = (const float*)d_in[7];
    const float* U2_2 = (const float*)d_in[8];
    const float* U3_2 = (const float*)d_in[9];
    const float* be_2 = (const float*)d_in[10];
    const float* Ve_2 = (const float*)d_in[11];
    const float* c2w  = (const float*)d_in[14];
    const float* c2b  = (const float*)d_in[15];
    float* out = (float*)d_out;

    // Hyperbolic branch contributes exactly 0.0*finite -> skipped entirely.
    fused_kernel<<<NBLOCKS, NTHREADS>>>(x, U1_2, U2_2, U3_2, be_2, Ve_2, c2w, c2b, out);
}

// round 14
// speedup vs baseline: 1.0172x; 1.0172x over previous
#include <cuda_runtime.h>
#include <math.h>

#define N_NODES 8000
#define NT      (N_NODES * 12)        // 96000
#define NODES_PER_BLK 64
#define NBLOCKS 125                   // 8000/64, <=148 SMs -> all co-resident
#define NTHREADS 320

// Row-per-block partials: g_part[b][j]; rows 125..127 never written (stay 0.0
// from static zero-init) -> combine sums a fixed 128 rows in fixed order.
__device__ float    g_part[128][128];
__device__ unsigned g_arrive;         // monotonic epoch counter (never reset)

__global__ void __launch_bounds__(NTHREADS)
fused_kernel(const float* __restrict__ x,
             const float* __restrict__ U1,
             const float* __restrict__ U2,   // (5,8000) row-major
             const float* __restrict__ U3,
             const float* __restrict__ be,
             const float* __restrict__ Ve,
             const float* __restrict__ w,    // conv2_w (5,5,1,3) flat o*15+i*3+k
             const float* __restrict__ bias, // conv2_b (5,)
             float* __restrict__ out)
{
    __shared__ float sX [NODES_PER_BLK][61];      // x[nl][t*5+f], pad 61
    __shared__ float sX2[5][NODES_PER_BLK * 13];
    __shared__ float sP[2][120];                  // split-partials halves
    __shared__ float sQ[2][120];                  // combine halves
    __shared__ float sU1[NODES_PER_BLK];
    __shared__ float sU2[5][NODES_PER_BLK];
    __shared__ float sU3[5];
    __shared__ float sVe[144];
    __shared__ float sBe[144];
    __shared__ float sLhs[60];
    __shared__ float sM2[60];
    __shared__ float sS[12][12];
    __shared__ float sE[12][12];
    __shared__ float sAt[12][12];
    __shared__ float sW[75];
    __shared__ float sB[5];

    const int tid = threadIdx.x;
    const int b   = blockIdx.x;
    const int n0  = b * NODES_PER_BLK;

    // ---- Preamble: x tile + ALL small tensors in one overlapped burst ----
    {
        const float4* xp = (const float4*)(x + n0 * 60);
        #pragma unroll
        for (int r = 0; r < 3; r++) {
            const int j = tid + r * NTHREADS;
            float4 v = xp[j];
            const int n = j / 15, c = (j % 15) * 4;
            float* d = &sX[n][c];
            d[0] = v.x; d[1] = v.y; d[2] = v.z; d[3] = v.w;
        }
    }
    {   // sU2 covers all 320 threads
        const int f2 = tid / NODES_PER_BLK, nl = tid % NODES_PER_BLK;
        sU2[f2][nl] = U2[f2 * N_NODES + n0 + nl];
    }
    if (tid < NODES_PER_BLK)     sU1[tid]       = U1[n0 + tid];
    if (tid < 5)                 sU3[tid]       = U3[tid];
    if (tid < 144)               sVe[tid]       = Ve[tid];
    if (tid >= 144 && tid < 288) sBe[tid - 144] = be[tid - 144];
    if (tid < 75)                sW[tid]        = w[tid];
    if (tid >= 288 && tid < 293) sB[tid - 288]  = bias[tid - 288];
    __syncthreads();

    // ---- Pass-1 partials, 2-way node split (halves the serial chain) ----
    //   group h in {0,1}: h=0 -> threads 0..119, nodes 0..31
    //                     h=1 -> threads 160..279, nodes 32..63
    {
        int h = -1, j = 0;
        if (tid < 120)                    { h = 0; j = tid; }
        else if (tid >= 160 && tid < 280) { h = 1; j = tid - 160; }
        if (h >= 0) {
            const int base = h * 32;
            float acc = 0.f;
            if (j < 60) {
                #pragma unroll 8
                for (int i = 0; i < 32; i++)
                    acc += sX[base + i][j] * sU1[base + i];
            } else {
                const int jj = j - 60;
                const int f2 = jj / 12, t = jj % 12;
                float u3[5];
                #pragma unroll
                for (int f = 0; f < 5; f++) u3[f] = sU3[f];
                #pragma unroll 4
                for (int i = 0; i < 32; i++) {
                    const int nl = base + i;
                    float r = 0.f;
                    #pragma unroll
                    for (int f = 0; f < 5; f++) r += sX[nl][t * 5 + f] * u3[f];
                    acc += sU2[f2][nl] * r;
                }
            }
            sP[h][j] = acc;
        }
    }
    __syncthreads();
    if (tid < 120)
        g_part[b][tid] = sP[0][tid] + sP[1][tid];   // fixed order, coalesced row
    __syncthreads();                                 // order STGs before fence

    // ---- Grid barrier: single release fence + backoff spin ----
    if (tid == 0) {
        __threadfence();                 // release partials (one MEMBAR.GPU)
        unsigned old = atomicAdd(&g_arrive, 1u);
        const unsigned target = (old / (unsigned)NBLOCKS + 1u) * (unsigned)NBLOCKS;
        volatile unsigned* va = &g_arrive;
        while (*va < target) __nanosleep(128);
        __threadfence();                 // acquire
    }
    __syncthreads();

    // ---- Combine: (half q, j) sums 64 fixed rows, 4 independent chains ----
    if (tid < 240) {
        const int q = tid / 120, j = tid % 120;
        const float* p = &g_part[q * 64][0];
        float a0 = 0.f, a1 = 0.f, a2 = 0.f, a3 = 0.f;
        #pragma unroll
        for (int i = 0; i < 64; i += 4) {           // rows 125..127 read as 0
            a0 += __ldcg(p + (i + 0) * 128 + j);
            a1 += __ldcg(p + (i + 1) * 128 + j);
            a2 += __ldcg(p + (i + 2) * 128 + j);
            a3 += __ldcg(p + (i + 3) * 128 + j);
        }
        sQ[q][j] = (a0 + a1) + (a2 + a3);           // fixed order
    }
    __syncthreads();
    if (tid < 120) {
        float s = sQ[0][tid] + sQ[1][tid];
        if (tid < 60) sLhs[tid] = s;
        else          sM2[tid - 60] = s;
    }
    __syncthreads();

    // ---- At2 distributed: 144-thread phases ----
    if (tid < 144) {
        const int t1 = tid / 12, t2 = tid % 12;
        float p = 0.f;
        #pragma unroll
        for (int f = 0; f < 5; f++) p += sLhs[t1 * 5 + f] * sM2[f * 12 + t2];
        p += sBe[tid];
        sS[t1][t2] = 1.f / (1.f + __expf(-p));
    }
    __syncthreads();
    if (tid < 144) {
        const int t1 = tid / 12, t2 = tid % 12;
        float e = 0.f;
        #pragma unroll
        for (int k = 0; k < 12; k++) e += sVe[t1 * 12 + k] * sS[k][t2];
        sE[t1][t2] = e;
    }
    __syncthreads();
    if (tid < 12) {                                 // column softmax
        const int t2 = tid;
        float E[12];
        float mx = -1e30f;
        #pragma unroll
        for (int k = 0; k < 12; k++) { E[k] = sE[k][t2]; mx = fmaxf(mx, E[k]); }
        float den = 0.f;
        #pragma unroll
        for (int k = 0; k < 12; k++) { E[k] = __expf(E[k] - mx); den += E[k]; }
        const float inv = 1.f / den;
        #pragma unroll
        for (int k = 0; k < 12; k++) sAt[k][t2] = E[k] * inv;
    }
    __syncthreads();

    // ---- Phase B: thread (f, nl) -> x2[f][nl][0..11] ----
    {
        const int f  = tid / NODES_PER_BLK;
        const int nl = tid % NODES_PER_BLK;
        float xr[12];
        #pragma unroll
        for (int tp = 0; tp < 12; tp++) xr[tp] = sX[nl][tp * 5 + f];
        float* dst = &sX2[f][nl * 13];
        #pragma unroll
        for (int t = 0; t < 12; t++) {
            float a = 0.f;
            #pragma unroll
            for (int tp = 0; tp < 12; tp++) a += xr[tp] * sAt[tp][t];
            dst[t] = a;
        }
    }
    __syncthreads();

    // ---- Phase C: thread (o, nl) -> conv plane + coalesced 48B store ----
    {
        const int o  = tid / NODES_PER_BLK;
        const int nl = tid % NODES_PER_BLK;
        float wr[15];
        #pragma unroll
        for (int i = 0; i < 15; i++) wr[i] = sW[o * 15 + i];
        const float b0 = sB[o];

        float yr[12];
        #pragma unroll
        for (int t = 0; t < 12; t++) yr[t] = b0;
        #pragma unroll
        for (int fi = 0; fi < 5; fi++) {
            const float* s = &sX2[fi][nl * 13];
            float v[12];
            #pragma unroll
            for (int t = 0; t < 12; t++) v[t] = s[t];
            const float w0 = wr[fi * 3 + 0], w1 = wr[fi * 3 + 1], w2 = wr[fi * 3 + 2];
            #pragma unroll
            for (int t = 0; t < 12; t++) {
                float a = w1 * v[t];
                if (t > 0)  a += w0 * v[t - 1];
                if (t < 11) a += w2 * v[t + 1];
                yr[t] += a;
            }
        }
        // raw-reshape output: flat = o*N*T + n*T + t
        float4* op = (float4*)(out + o * NT + (n0 + nl) * 12);
        op[0] = make_float4(yr[0], yr[1], yr[2],  yr[3]);
        op[1] = make_float4(yr[4], yr[5], yr[6],  yr[7]);
        op[2] = make_float4(yr[8], yr[9], yr[10], yr[11]);
    }
}

extern "C" void kernel_launch(void* const* d_in, const int* in_sizes, int n_in,
                              void* d_out, int out_size)
{
    // metadata order: x, adj, U1_1, U2_1, U3_1, be_1, Ve_1,
    //                 U1_2, U2_2, U3_2, be_2, Ve_2,
    //                 conv1_w, conv1_b, conv2_w, conv2_b, W_hgc, b_hgc
    const float* x    = (const float*)d_in[0];
    const float* U1_2 = (const float*)d_in[7];
    const float* U2_2 = (const float*)d_in[8];
    const float* U3_2 = (const float*)d_in[9];
    const float* be_2 = (const float*)d_in[10];
    const float* Ve_2 = (const float*)d_in[11];
    const float* c2w  = (const float*)d_in[14];
    const float* c2b  = (const float*)d_in[15];
    float* out = (float*)d_out;

    // Hyperbolic branch contributes exactly 0.0*finite -> skipped entirely.
    fused_kernel<<<NBLOCKS, NTHREADS>>>(x, U1_2, U2_2, U3_2, be_2, Ve_2, c2w, c2b, out);
}